// round 2
// baseline (speedup 1.0000x reference)
#include <cuda_runtime.h>
#include <stdint.h>
#include <math.h>

// Problem dims (fixed by setup_inputs)
#define CB 4
#define CN 1024
#define CD 512
#define CH 8
#define DH 64
#define LA 144        // augmented vector length (131 used, padded to 144)
#define NBH (CB*CH)   // 32

// ---------------- scratch (__device__ globals; no allocation allowed) ----------------
__device__ __align__(16) float g_x [CB*CN*1536];          // x_tan @ W^T + b  (4096 x 1536)
__device__ __align__(16) float g_v [CB*CN*1024];          // v_tan @ W^T + b  (first 1024 cols)
__device__ __align__(16) float g_Qa[(size_t)NBH*CN*LA];   // augmented Q rows
__device__ __align__(16) float g_Ka[(size_t)NBH*CN*LA];   // augmented K rows
__device__ unsigned g_r1[CN*32];   // bool(A)   rows (with diag)
__device__ unsigned g_r2[CN*32];   // bool(A^2) rows (with diag)
__device__ unsigned g_m1[CN*32];   // diag-cleared masks
__device__ unsigned g_m2[CN*32];
__device__ unsigned g_m3[CN*32];
__device__ unsigned g_rowM[NBH*CN]; // encoded row max
__device__ float    g_rowZ[NBH*CN]; // row sum of exp

// ---------------- helpers ----------------
typedef unsigned long long ull;
union F4U { float4 f; ull u[2]; float s[4]; };

__device__ __forceinline__ void fma2(ull& c, ull a, ull b) {
    asm("fma.rn.f32x2 %0, %1, %2, %0;" : "+l"(c) : "l"(a), "l"(b));
}
__device__ __forceinline__ ull bcast2(float x) {
    ull r; unsigned xi = __float_as_uint(x);
    asm("mov.b64 %0, {%1, %1};" : "=l"(r) : "r"(xi));
    return r;
}
__device__ __forceinline__ float2 unpk(ull v) {
    unsigned a, b;
    asm("mov.b64 {%0, %1}, %2;" : "=r"(a), "=r"(b) : "l"(v));
    float2 r; r.x = __uint_as_float(a); r.y = __uint_as_float(b); return r;
}
__device__ __forceinline__ unsigned fenc(float f) {
    unsigned u = __float_as_uint(f);
    return (u & 0x80000000u) ? ~u : (u | 0x80000000u);
}
__device__ __forceinline__ float fdec(unsigned u) {
    return __uint_as_float((u & 0x80000000u) ? (u ^ 0x80000000u) : ~u);
}

// ---------------- init: clear encoded row-max ----------------
__global__ void k_init() {
    int idx = blockIdx.x * blockDim.x + threadIdx.x;
    if (idx < NBH * CN) g_rowM[idx] = 0u;   // smallest encoded value
}

// ---------------- K1: QKV GEMM  C = A @ W^T + bias (NT, fp32, f32x2) ----------------
// A: 4096 x 512.  W: Ncols x 512.  C: 4096 x Ncols. Tile 128x128x16, 256 thr, 8x8/thr.
__global__ __launch_bounds__(256) void gemm_qkv(const float* __restrict__ A,
                                                const float* __restrict__ W,
                                                const float* __restrict__ bias,
                                                int which, int Ncols) {
    __shared__ float As[16][132];
    __shared__ float Bs[16][132];
    float* C = which ? g_v : g_x;
    int t = threadIdx.x;
    int tx = t & 15, ty = t >> 4;
    int m0 = blockIdx.y * 128, n0 = blockIdx.x * 128;
    int lr = t >> 1, lk = (t & 1) * 8;
    const float* Ap = A + (size_t)(m0 + lr) * 512 + lk;
    const float* Wp = W + (size_t)(n0 + lr) * 512 + lk;

    ull acc[8][4];
#pragma unroll
    for (int i = 0; i < 8; i++)
#pragma unroll
        for (int j = 0; j < 4; j++) acc[i][j] = 0ULL;

    for (int k0 = 0; k0 < 512; k0 += 16) {
        F4U a0, a1, b0, b1;
        a0.f = *(const float4*)(Ap + k0);
        a1.f = *(const float4*)(Ap + k0 + 4);
        b0.f = *(const float4*)(Wp + k0);
        b1.f = *(const float4*)(Wp + k0 + 4);
        __syncthreads();
#pragma unroll
        for (int q = 0; q < 4; q++) {
            As[lk + q][lr]     = a0.s[q];
            As[lk + 4 + q][lr] = a1.s[q];
            Bs[lk + q][lr]     = b0.s[q];
            Bs[lk + 4 + q][lr] = b1.s[q];
        }
        __syncthreads();
#pragma unroll
        for (int kk = 0; kk < 16; kk++) {
            F4U av0, av1, bv0, bv1;
            av0.f = *(const float4*)&As[kk][ty * 4];
            av1.f = *(const float4*)&As[kk][ty * 4 + 64];
            bv0.f = *(const float4*)&Bs[kk][tx * 4];
            bv1.f = *(const float4*)&Bs[kk][tx * 4 + 64];
#pragma unroll
            for (int i = 0; i < 8; i++) {
                float am = (i < 4) ? av0.s[i] : av1.s[i - 4];
                ull ap = bcast2(am);
                fma2(acc[i][0], ap, bv0.u[0]);
                fma2(acc[i][1], ap, bv0.u[1]);
                fma2(acc[i][2], ap, bv1.u[0]);
                fma2(acc[i][3], ap, bv1.u[1]);
            }
        }
    }

    F4U bias0, bias1;
    bias0.f = *(const float4*)(bias + n0 + tx * 4);
    bias1.f = *(const float4*)(bias + n0 + tx * 4 + 64);
#pragma unroll
    for (int i = 0; i < 8; i++) {
        int m = (i < 4) ? (ty * 4 + i) : (64 + ty * 4 + (i - 4));
        float* cp = C + (size_t)(m0 + m) * Ncols + n0;
        float2 p0 = unpk(acc[i][0]), p1 = unpk(acc[i][1]);
        float4 o;
        o.x = p0.x + bias0.s[0]; o.y = p0.y + bias0.s[1];
        o.z = p1.x + bias0.s[2]; o.w = p1.y + bias0.s[3];
        *(float4*)(cp + tx * 4) = o;
        p0 = unpk(acc[i][2]); p1 = unpk(acc[i][3]);
        o.x = p0.x + bias1.s[0]; o.y = p0.y + bias1.s[1];
        o.z = p1.x + bias1.s[2]; o.w = p1.y + bias1.s[3];
        *(float4*)(cp + tx * 4 + 64) = o;
    }
}

// ---------------- K2: topo bitsets ----------------
__global__ void k_bits1(const float* __restrict__ A) {
    int i = blockIdx.x * 8 + (threadIdx.x >> 5);
    int lane = threadIdx.x & 31;
    const float* row = A + (size_t)i * CN;
    unsigned myw = 0;
#pragma unroll
    for (int j = 0; j < 32; j++) {
        unsigned bal = __ballot_sync(0xffffffffu, row[j * 32 + lane] > 0.0f);
        if (lane == j) myw = bal;
    }
    g_r1[i * 32 + lane] = myw;
    unsigned m = myw;
    if ((i >> 5) == lane) m &= ~(1u << (i & 31));
    g_m1[i * 32 + lane] = m;
}

__global__ void k_bits2() {
    int i = blockIdx.x * 8 + (threadIdx.x >> 5);
    int lane = threadIdx.x & 31;
    unsigned acc = 0;
    for (int kw = 0; kw < 32; kw++) {
        unsigned sel = g_r1[i * 32 + kw];
        while (sel) {
            int b = __ffs(sel) - 1; sel &= sel - 1;
            acc |= g_r1[(kw * 32 + b) * 32 + lane];
        }
    }
    g_r2[i * 32 + lane] = acc;
    unsigned m = acc;
    if ((i >> 5) == lane) m &= ~(1u << (i & 31));
    g_m2[i * 32 + lane] = m;
}

__global__ void k_bits3() {
    int i = blockIdx.x * 8 + (threadIdx.x >> 5);
    int lane = threadIdx.x & 31;
    unsigned acc = 0;
    for (int kw = 0; kw < 32; kw++) {
        unsigned sel = g_r2[i * 32 + kw];
        while (sel) {
            int b = __ffs(sel) - 1; sel &= sel - 1;
            acc |= g_r1[(kw * 32 + b) * 32 + lane];
        }
    }
    unsigned m = acc;
    if ((i >> 5) == lane) m &= ~(1u << (i & 31));
    g_m3[i * 32 + lane] = m;
}

// ---------------- K3: build augmented Q~/K~ rows ----------------
__global__ void k_augment(const float* __restrict__ tau) {
    int bn = blockIdx.x;                  // 0..4095 = b*1024+n
    int h = threadIdx.x >> 5;             // 8 warps = 8 heads
    int lane = threadIdx.x & 31;
    int b = bn >> 10, n = bn & 1023;
    const float* xr = g_x + (size_t)bn * 1536;
    const float* vr = g_v + (size_t)bn * 1024;
    float tc = fmaxf(tau[h], 1e-3f);
    float itc = 1.0f / tc;

    float2 q  = *(const float2*)(xr + h * 64 + lane * 2);
    float2 k  = *(const float2*)(xr + 512 + h * 64 + lane * 2);
    float2 vq = *(const float2*)(vr + h * 64 + lane * 2);
    float2 vk = *(const float2*)(vr + 512 + h * 64 + lane * 2);

    float sq  = q.x * q.x + q.y * q.y;
    float sk  = k.x * k.x + k.y * k.y;
    float svq = vq.x * vq.x + vq.y * vq.y;
    float svk = vk.x * vk.x + vk.y * vk.y;
#pragma unroll
    for (int m = 16; m; m >>= 1) {
        sq  += __shfl_xor_sync(0xffffffffu, sq, m);
        sk  += __shfl_xor_sync(0xffffffffu, sk, m);
        svq += __shfl_xor_sync(0xffffffffu, svq, m);
        svk += __shfl_xor_sync(0xffffffffu, svk, m);
    }
    // bound tangent + exp_map0
    float nq0 = sqrtf(fmaxf(sq, 1e-7f));
    float scq = fminf(3.0f / nq0, 1.0f);
    float nq  = sqrtf(fmaxf(sq * scq * scq, 1e-14f));
    float cq  = coshf(nq), fq = sinhf(nq) / nq * scq;

    float nk0 = sqrtf(fmaxf(sk, 1e-7f));
    float sck = fminf(3.0f / nk0, 1.0f);
    float nk  = sqrtf(fmaxf(sk * sck * sck, 1e-14f));
    float ck  = coshf(nk), fk = sinhf(nk) / nk * sck;

    int bh = b * CH + h;
    float* Q = g_Qa + ((size_t)bh * CN + n) * LA;
    float* K = g_Ka + ((size_t)bh * CN + n) * LA;
    const float R2 = 1.4142135623730951f;
    float2 w;
    float fqi = fq * itc;
    w.x = q.x * fqi;  w.y = q.y * fqi;  *(float2*)(Q + lane * 2) = w;
    w.x = vq.x * R2;  w.y = vq.y * R2;  *(float2*)(Q + 64 + lane * 2) = w;
    w.x = k.x * fk;   w.y = k.y * fk;   *(float2*)(K + lane * 2) = w;
    w.x = vk.x * R2;  w.y = vk.y * R2;  *(float2*)(K + 64 + lane * 2) = w;
    if (lane == 0) {
        Q[128] = -cq * itc; Q[129] = 1.0f;       Q[130] = -svq;
        K[128] = ck;        K[129] = itc - svk;  K[130] = 1.0f;
    }
    if (lane < 13) { Q[131 + lane] = 0.0f; K[131 + lane] = 0.0f; }
}

// ---------------- K4: score GEMM (Q~ K~^T) + topo + row max, write raw S ----------------
__global__ __launch_bounds__(256) void k_score(const float* __restrict__ gam,
                                               float* __restrict__ S) {
    __shared__ float As[16][132];
    __shared__ float Bs[16][132];
    int t = threadIdx.x;
    int tx = t & 15, ty = t >> 4;
    int bh = blockIdx.z;
    int m0 = blockIdx.y * 128, n0 = blockIdx.x * 128;
    int lr = t >> 1, lk = (t & 1) * 8;
    const float* Ap = g_Qa + ((size_t)bh * CN + m0 + lr) * LA + lk;
    const float* Bp = g_Ka + ((size_t)bh * CN + n0 + lr) * LA + lk;

    ull acc[8][4];
#pragma unroll
    for (int i = 0; i < 8; i++)
#pragma unroll
        for (int j = 0; j < 4; j++) acc[i][j] = 0ULL;

    for (int k0 = 0; k0 < LA; k0 += 16) {
        F4U a0, a1, b0, b1;
        a0.f = *(const float4*)(Ap + k0);
        a1.f = *(const float4*)(Ap + k0 + 4);
        b0.f = *(const float4*)(Bp + k0);
        b1.f = *(const float4*)(Bp + k0 + 4);
        __syncthreads();
#pragma unroll
        for (int q = 0; q < 4; q++) {
            As[lk + q][lr]     = a0.s[q];
            As[lk + 4 + q][lr] = a1.s[q];
            Bs[lk + q][lr]     = b0.s[q];
            Bs[lk + 4 + q][lr] = b1.s[q];
        }
        __syncthreads();
#pragma unroll
        for (int kk = 0; kk < 16; kk++) {
            F4U av0, av1, bv0, bv1;
            av0.f = *(const float4*)&As[kk][ty * 4];
            av1.f = *(const float4*)&As[kk][ty * 4 + 64];
            bv0.f = *(const float4*)&Bs[kk][tx * 4];
            bv1.f = *(const float4*)&Bs[kk][tx * 4 + 64];
#pragma unroll
            for (int i = 0; i < 8; i++) {
                float am = (i < 4) ? av0.s[i] : av1.s[i - 4];
                ull ap = bcast2(am);
                fma2(acc[i][0], ap, bv0.u[0]);
                fma2(acc[i][1], ap, bv0.u[1]);
                fma2(acc[i][2], ap, bv1.u[0]);
                fma2(acc[i][3], ap, bv1.u[1]);
            }
        }
    }

    int h = bh & 7;
    float g0 = gam[h * 3 + 0], g1 = gam[h * 3 + 1], g2 = gam[h * 3 + 2];
    bool use23 = (g1 != 0.0f) || (g2 != 0.0f);
    float* Sb = S + ((size_t)bh * CN) * CN;

#pragma unroll
    for (int i = 0; i < 8; i++) {
        int row = m0 + ((i < 4) ? (ty * 4 + i) : (64 + ty * 4 + i - 4));
        float rmax = -3.4e38f;
#pragma unroll
        for (int half = 0; half < 2; half++) {
            int j0 = n0 + tx * 4 + half * 64;
            unsigned w1 = g_m1[row * 32 + (j0 >> 5)];
            unsigned w2 = 0, w3 = 0;
            if (use23) {
                w2 = g_m2[row * 32 + (j0 >> 5)];
                w3 = g_m3[row * 32 + (j0 >> 5)];
            }
            float2 p0 = unpk(acc[i][half * 2]);
            float2 p1 = unpk(acc[i][half * 2 + 1]);
            float sv[4] = { p0.x, p0.y, p1.x, p1.y };
#pragma unroll
            for (int c = 0; c < 4; c++) {
                int sh = (j0 + c) & 31;
                float tadd = ((w1 >> sh) & 1) ? g0 : 0.0f;
                if (use23) {
                    tadd += ((w2 >> sh) & 1) ? g1 : 0.0f;
                    tadd += ((w3 >> sh) & 1) ? g2 : 0.0f;
                }
                sv[c] += tadd;
                rmax = fmaxf(rmax, sv[c]);
            }
            float4 o = make_float4(sv[0], sv[1], sv[2], sv[3]);
            *(float4*)(Sb + (size_t)row * CN + j0) = o;
        }
#pragma unroll
        for (int m = 8; m; m >>= 1)
            rmax = fmaxf(rmax, __shfl_xor_sync(0xffffffffu, rmax, m));
        if (tx == 0) atomicMax(&g_rowM[bh * CN + row], fenc(rmax));
    }
}

// ---------------- K5: row sums of exp(S - M) ----------------
__global__ void k_rowsum(const float* __restrict__ S) {
    int row = blockIdx.x * 8 + (threadIdx.x >> 5);   // 0..32767 = bh*1024 + i
    int lane = threadIdx.x & 31;
    float M = fdec(g_rowM[row]);
    const float* Sr = S + (size_t)row * CN;
    float sum = 0.0f;
#pragma unroll
    for (int w = 0; w < 8; w++) {
        float4 v = *(const float4*)(Sr + (w * 32 + lane) * 4);
        sum += __expf(v.x - M) + __expf(v.y - M) + __expf(v.z - M) + __expf(v.w - M);
    }
#pragma unroll
    for (int m = 16; m; m >>= 1) sum += __shfl_xor_sync(0xffffffffu, sum, m);
    if (lane == 0) g_rowZ[row] = sum;
}

// ---------------- K6: normalize attn (write) + z = P @ v_s ----------------
__global__ __launch_bounds__(256) void k_zattn(float* __restrict__ S, float* __restrict__ z) {
    __shared__ float Vs[32 * 64];
    __shared__ float Ps[128 * 33];
    __shared__ float sM[128];
    __shared__ float sR[128];
    int t = threadIdx.x;
    int bh = blockIdx.y; int b = bh >> 3, h = bh & 7;
    int i0 = blockIdx.x * 128;
    if (t < 128) {
        int r = bh * CN + i0 + t;
        sM[t] = fdec(g_rowM[r]);
        sR[t] = 1.0f / g_rowZ[r];
    }
    int tx = t & 15, ty = t >> 4;
    ull acc[8][2];
#pragma unroll
    for (int i = 0; i < 8; i++) { acc[i][0] = 0ULL; acc[i][1] = 0ULL; }
    float* Sbase = S + ((size_t)bh * CN + i0) * CN;

    for (int k0 = 0; k0 < CN; k0 += 32) {
        __syncthreads();   // protect smem from previous iteration's readers
        // stage V chunk [32 k][64 d]
        {
            int kk = t >> 3, fg = t & 7;
            const float* vr = g_x + (size_t)(b * CN + k0 + kk) * 1536 + 1024 + h * 64;
            *(float4*)(Vs + kk * 64 + fg * 4)      = *(const float4*)(vr + fg * 4);
            *(float4*)(Vs + kk * 64 + 32 + fg * 4) = *(const float4*)(vr + 32 + fg * 4);
        }
        // stage P chunk [128 rows][32 k]: exp, normalize, write attn out + smem
        {
            int r = t >> 1;
            float M = sM[r], ri = sR[r];
            float* Srow = Sbase + (size_t)r * CN + k0 + (t & 1) * 16;
            float* Prow = Ps + r * 33 + (t & 1) * 16;
#pragma unroll
            for (int w2 = 0; w2 < 4; w2++) {
                float4 v = *(float4*)(Srow + w2 * 4);
                v.x = __expf(v.x - M) * ri; v.y = __expf(v.y - M) * ri;
                v.z = __expf(v.z - M) * ri; v.w = __expf(v.w - M) * ri;
                *(float4*)(Srow + w2 * 4) = v;   // normalized attn output (in place)
                Prow[w2 * 4 + 0] = v.x; Prow[w2 * 4 + 1] = v.y;
                Prow[w2 * 4 + 2] = v.z; Prow[w2 * 4 + 3] = v.w;
            }
        }
        __syncthreads();
#pragma unroll 4
        for (int k = 0; k < 32; k++) {
            F4U vv; vv.f = *(const float4*)(Vs + k * 64 + tx * 4);
#pragma unroll
            for (int i = 0; i < 8; i++) {
                float p = Ps[(ty * 8 + i) * 33 + k];
                ull pb = bcast2(p);
                fma2(acc[i][0], pb, vv.u[0]);
                fma2(acc[i][1], pb, vv.u[1]);
            }
        }
    }
#pragma unroll
    for (int i = 0; i < 8; i++) {
        int n = i0 + ty * 8 + i;
        float2 a = unpk(acc[i][0]), c2 = unpk(acc[i][1]);
        float4 o = make_float4(a.x, a.y, c2.x, c2.y);
        *(float4*)(z + (size_t)(b * CN + n) * CD + h * 64 + tx * 4) = o;
    }
}

// ---------------- launch ----------------
extern "C" void kernel_launch(void* const* d_in, const int* in_sizes, int n_in,
                              void* d_out, int out_size) {
    const float* x_tan     = (const float*)d_in[0];
    const float* v_tan     = (const float*)d_in[1];
    const float* topo_bias = (const float*)d_in[2];
    const float* qkv_w     = (const float*)d_in[3];
    const float* qkv_b     = (const float*)d_in[4];
    const float* tau       = (const float*)d_in[5];
    const float* gam       = (const float*)d_in[6];
    float* z    = (float*)d_out;                       // z_tan: (4,1024,512)
    float* attn = z + (size_t)CB * CN * CD;            // attn:  (4,8,1024,1024)

    k_init<<<128, 256>>>();
    gemm_qkv<<<dim3(12, 32), 256>>>(x_tan, qkv_w, qkv_b, 0, 1536);
    gemm_qkv<<<dim3(8, 32), 256>>>(v_tan, qkv_w, qkv_b, 1, 1024);
    k_bits1<<<128, 256>>>(topo_bias);
    k_bits2<<<128, 256>>>();
    k_bits3<<<128, 256>>>();
    k_augment<<<4096, 256>>>(tau);
    k_score<<<dim3(8, 8, 32), 256>>>(gam, attn);
    k_rowsum<<<4096, 256>>>(attn);
    k_zattn<<<dim3(8, 32), 256>>>(attn, z);
}

// round 5
// speedup vs baseline: 1.3661x; 1.3661x over previous
#include <cuda_runtime.h>
#include <cuda_bf16.h>
#include <stdint.h>
#include <math.h>

#define CB 4
#define CN 1024
#define CD 512
#define CH 8
#define NBH (CB*CH)

typedef unsigned long long ull;

// ---------------- scratch (__device__ globals) ----------------
__device__ __align__(16) float g_x[CB*CN*1536];      // qkv(x_tan): 4096 x 1536
__device__ __align__(16) float g_v[CB*CN*1024];      // qkv(v_tan): 4096 x 1024
__device__ __align__(16) __nv_bfloat16 g_xs[2][CB*CN*512];
__device__ __align__(16) __nv_bfloat16 g_vs[2][CB*CN*512];
__device__ __align__(16) __nv_bfloat16 g_ws[2][1536*512];
__device__ __align__(16) __nv_bfloat16 g_Qs[2][(size_t)NBH*CN*128];
__device__ __align__(16) __nv_bfloat16 g_Ks[2][(size_t)NBH*CN*128];
__device__ float g_su [NBH*CN];   // -cosh(q)/tau
__device__ float g_swv[NBH*CN];   // cosh(k)
__device__ float g_cbv[NBH*CN];   // 1/tau - |vk|^2
__device__ float g_rbv[NBH*CN];   // -|vq|^2
__device__ unsigned g_r1[CN*32], g_r2[CN*32];
__device__ unsigned g_m1[CN*32], g_m2[CN*32], g_m3[CN*32];
__device__ unsigned g_rowM[NBH*CN];
__device__ float    g_rowZ[NBH*CN];

// ---------------- generic helpers ----------------
union F4U { float4 f; ull u[2]; float s[4]; };

__device__ __forceinline__ void fma2(ull& c, ull a, ull b) {
    asm("fma.rn.f32x2 %0, %1, %2, %0;" : "+l"(c) : "l"(a), "l"(b));
}
__device__ __forceinline__ ull bcast2(float x) {
    ull r; unsigned xi = __float_as_uint(x);
    asm("mov.b64 %0, {%1, %1};" : "=l"(r) : "r"(xi));
    return r;
}
__device__ __forceinline__ float2 unpk(ull v) {
    unsigned a, b;
    asm("mov.b64 {%0, %1}, %2;" : "=r"(a), "=r"(b) : "l"(v));
    float2 r; r.x = __uint_as_float(a); r.y = __uint_as_float(b); return r;
}
__device__ __forceinline__ unsigned fenc(float f) {
    unsigned u = __float_as_uint(f);
    return (u & 0x80000000u) ? ~u : (u | 0x80000000u);
}
__device__ __forceinline__ float fdec(unsigned u) {
    return __uint_as_float((u & 0x80000000u) ? (u ^ 0x80000000u) : ~u);
}
__device__ __forceinline__ uint32_t smem_u32(const void* p) {
    uint32_t a;
    asm("{ .reg .u64 t; cvta.to.shared.u64 t, %1; cvt.u32.u64 %0, t; }" : "=r"(a) : "l"(p));
    return a;
}

// ---------------- mma.sync helpers (sm_80 feature set; valid on sm_100 base target) ----------------
__device__ __forceinline__ void ldsm4(uint32_t* r, uint32_t addr) {
    asm volatile("ldmatrix.sync.aligned.m8n8.x4.shared.b16 {%0,%1,%2,%3}, [%4];"
                 : "=r"(r[0]), "=r"(r[1]), "=r"(r[2]), "=r"(r[3]) : "r"(addr));
}
__device__ __forceinline__ void hmma(float* c, const uint32_t* a, const uint32_t* b) {
    asm volatile("mma.sync.aligned.m16n8k16.row.col.f32.bf16.bf16.f32 "
                 "{%0,%1,%2,%3}, {%4,%5,%6,%7}, {%8,%9}, {%0,%1,%2,%3};"
                 : "+f"(c[0]), "+f"(c[1]), "+f"(c[2]), "+f"(c[3])
                 : "r"(a[0]), "r"(a[1]), "r"(a[2]), "r"(a[3]), "r"(b[0]), "r"(b[1]));
}

// SW128 swizzle for 128-byte rows (64 bf16 per row), 16B granularity
__device__ __forceinline__ unsigned swz(int row, int col) {
    unsigned b = (unsigned)row * 128u + (unsigned)col * 2u;
    return b ^ ((b >> 3) & 0x70);
}

#define PLANE 16384
#define SMEM_BYTES (4*PLANE)   // 64 KB: A hi/lo + B hi/lo

// load one 128x64 bf16 plane into swizzled smem (256 threads)
__device__ __forceinline__ void load_plane(const __nv_bfloat16* __restrict__ src,
                                           size_t row0, int stride, int k0, char* plane) {
    int t = threadIdx.x;
#pragma unroll
    for (int it = 0; it < 4; it++) {
        int idx = it * 256 + t;
        int row = idx >> 3;
        int col = (idx & 7) * 8;
        uint4 v = *(const uint4*)(src + (row0 + row) * (size_t)stride + (k0 + col));
        *(uint4*)(plane + swz(row, col)) = v;
    }
}

// one 64-K chunk of warp-level MMA: acc += A_plane * B_plane^T
__device__ __forceinline__ void mma_chunk(float acc[4][4][4], uint32_t aBase, uint32_t bBase,
                                          int m_warp, int n_warp, int lane) {
#pragma unroll
    for (int ks = 0; ks < 4; ks++) {
        int kc = ks * 16;
        uint32_t a[4][4], b[2][4];
#pragma unroll
        for (int mi = 0; mi < 4; mi++) {
            int row = m_warp + mi * 16 + (lane & 15);
            int col = kc + (lane >> 4) * 8;
            ldsm4(a[mi], aBase + swz(row, col));
        }
#pragma unroll
        for (int np = 0; np < 2; np++) {
            int row = n_warp + np * 16 + ((lane >> 4) << 3) + (lane & 7);
            int col = kc + ((lane >> 3) & 1) * 8;
            ldsm4(b[np], bBase + swz(row, col));
        }
#pragma unroll
        for (int mi = 0; mi < 4; mi++)
#pragma unroll
            for (int ni = 0; ni < 4; ni++)
                hmma(acc[mi][ni], a[mi], b[ni >> 1] + (ni & 1) * 2);
    }
}

// ---------------- init ----------------
__global__ void k_init() {
    int idx = blockIdx.x * blockDim.x + threadIdx.x;
    if (idx < NBH * CN) g_rowM[idx] = 0u;
}

// ---------------- split fp32 -> bf16 hi/lo planes ----------------
__device__ __forceinline__ void split2(float a, __nv_bfloat16& o0, __nv_bfloat16& o1) {
    o0 = __float2bfloat16(a);
    o1 = __float2bfloat16(a - __bfloat162float(o0));
}

__global__ void k_split(const float* __restrict__ A, int which, int total4) {
    int i = blockIdx.x * blockDim.x + threadIdx.x;
    if (i >= total4) return;
    __nv_bfloat16 *p0, *p1;
    if (which == 0)      { p0 = g_xs[0]; p1 = g_xs[1]; }
    else if (which == 1) { p0 = g_vs[0]; p1 = g_vs[1]; }
    else                 { p0 = g_ws[0]; p1 = g_ws[1]; }
    float4 a = *(const float4*)(A + (size_t)i * 4);
    __nv_bfloat16 x0, x1, y0, y1, z0, z1, w0, w1;
    split2(a.x, x0, x1); split2(a.y, y0, y1);
    split2(a.z, z0, z1); split2(a.w, w0, w1);
    size_t o = (size_t)i * 4;
    *(__nv_bfloat162*)(p0 + o)     = __halves2bfloat162(x0, y0);
    *(__nv_bfloat162*)(p0 + o + 2) = __halves2bfloat162(z0, w0);
    *(__nv_bfloat162*)(p1 + o)     = __halves2bfloat162(x1, y1);
    *(__nv_bfloat162*)(p1 + o + 2) = __halves2bfloat162(z1, w1);
}

// ---------------- MMA GEMM: C = A @ W^T + bias (K=512, 8 chunks x 3 passes) ----------------
__global__ __launch_bounds__(256) void mma_qkv(const float* __restrict__ bias, int which, int Ncols) {
    extern __shared__ char smem[];
    uint32_t sb = smem_u32(smem);
    int t = threadIdx.x, lane = t & 31, w = t >> 5;
    int m_warp = (w & 1) * 64, n_warp = (w >> 1) * 32;
    int n0 = blockIdx.x * 128, m0 = blockIdx.y * 128;
    const __nv_bfloat16* A0 = which ? g_vs[0] : g_xs[0];
    const __nv_bfloat16* A1 = which ? g_vs[1] : g_xs[1];

    float acc[4][4][4];
#pragma unroll
    for (int a = 0; a < 4; a++)
#pragma unroll
        for (int b = 0; b < 4; b++)
#pragma unroll
            for (int c = 0; c < 4; c++) acc[a][b][c] = 0.0f;

    for (int ch = 0; ch < 8; ch++) {
        int k0 = ch * 64;
        __syncthreads();
        load_plane(A0,      (size_t)m0, 512, k0, smem + 0 * PLANE);
        load_plane(A1,      (size_t)m0, 512, k0, smem + 1 * PLANE);
        load_plane(g_ws[0], (size_t)n0, 512, k0, smem + 2 * PLANE);
        load_plane(g_ws[1], (size_t)n0, 512, k0, smem + 3 * PLANE);
        __syncthreads();
        mma_chunk(acc, sb + 0 * PLANE, sb + 2 * PLANE, m_warp, n_warp, lane); // hi*hi
        mma_chunk(acc, sb + 0 * PLANE, sb + 3 * PLANE, m_warp, n_warp, lane); // hi*lo
        mma_chunk(acc, sb + 1 * PLANE, sb + 2 * PLANE, m_warp, n_warp, lane); // lo*hi
    }

    float* C = which ? g_v : g_x;
#pragma unroll
    for (int ni = 0; ni < 4; ni++) {
        int col = n0 + n_warp + ni * 8 + (lane & 3) * 2;
        float b0 = bias[col], b1 = bias[col + 1];
#pragma unroll
        for (int mi = 0; mi < 4; mi++) {
#pragma unroll
            for (int r2 = 0; r2 < 2; r2++) {
                int row = m0 + m_warp + mi * 16 + (lane >> 2) + r2 * 8;
                float2 o;
                o.x = acc[mi][ni][r2 * 2 + 0] + b0;
                o.y = acc[mi][ni][r2 * 2 + 1] + b1;
                *(float2*)(C + (size_t)row * Ncols + col) = o;
            }
        }
    }
}

// ---------------- topo bitsets ----------------
__global__ void k_bits1(const float* __restrict__ A) {
    int i = blockIdx.x * 8 + (threadIdx.x >> 5);
    int lane = threadIdx.x & 31;
    const float* row = A + (size_t)i * CN;
    unsigned myw = 0;
#pragma unroll
    for (int j = 0; j < 32; j++) {
        unsigned bal = __ballot_sync(0xffffffffu, row[j * 32 + lane] > 0.0f);
        if (lane == j) myw = bal;
    }
    g_r1[i * 32 + lane] = myw;
    unsigned m = myw;
    if ((i >> 5) == lane) m &= ~(1u << (i & 31));
    g_m1[i * 32 + lane] = m;
}
__global__ void k_bits2() {
    int i = blockIdx.x * 8 + (threadIdx.x >> 5);
    int lane = threadIdx.x & 31;
    unsigned acc = 0;
    for (int kw = 0; kw < 32; kw++) {
        unsigned sel = g_r1[i * 32 + kw];
        while (sel) {
            int b = __ffs(sel) - 1; sel &= sel - 1;
            acc |= g_r1[(kw * 32 + b) * 32 + lane];
        }
    }
    g_r2[i * 32 + lane] = acc;
    unsigned m = acc;
    if ((i >> 5) == lane) m &= ~(1u << (i & 31));
    g_m2[i * 32 + lane] = m;
}
__global__ void k_bits3() {
    int i = blockIdx.x * 8 + (threadIdx.x >> 5);
    int lane = threadIdx.x & 31;
    unsigned acc = 0;
    for (int kw = 0; kw < 32; kw++) {
        unsigned sel = g_r2[i * 32 + kw];
        while (sel) {
            int b = __ffs(sel) - 1; sel &= sel - 1;
            acc |= g_r1[(kw * 32 + b) * 32 + lane];
        }
    }
    unsigned m = acc;
    if ((i >> 5) == lane) m &= ~(1u << (i & 31));
    g_m3[i * 32 + lane] = m;
}

// ---------------- augment: build Q~/K~ bf16 hi/lo + side vectors ----------------
__device__ __forceinline__ void sp2(__nv_bfloat16* p0, __nv_bfloat16* p1,
                                    size_t off, float a, float b) {
    __nv_bfloat16 a0, a1, b0, b1;
    split2(a, a0, a1);
    split2(b, b0, b1);
    *(__nv_bfloat162*)(p0 + off) = __halves2bfloat162(a0, b0);
    *(__nv_bfloat162*)(p1 + off) = __halves2bfloat162(a1, b1);
}

__global__ void k_augment(const float* __restrict__ tau) {
    int bn = blockIdx.x;
    int h = threadIdx.x >> 5, lane = threadIdx.x & 31;
    int b = bn >> 10, n = bn & 1023;
    const float* xr = g_x + (size_t)bn * 1536;
    const float* vr = g_v + (size_t)bn * 1024;
    float tc = fmaxf(tau[h], 1e-3f), itc = 1.0f / tc;

    float2 q  = *(const float2*)(xr + h * 64 + lane * 2);
    float2 k  = *(const float2*)(xr + 512 + h * 64 + lane * 2);
    float2 vq = *(const float2*)(vr + h * 64 + lane * 2);
    float2 vk = *(const float2*)(vr + 512 + h * 64 + lane * 2);

    float sq  = q.x * q.x + q.y * q.y;
    float sk  = k.x * k.x + k.y * k.y;
    float svq = vq.x * vq.x + vq.y * vq.y;
    float svk = vk.x * vk.x + vk.y * vk.y;
#pragma unroll
    for (int m = 16; m; m >>= 1) {
        sq  += __shfl_xor_sync(0xffffffffu, sq, m);
        sk  += __shfl_xor_sync(0xffffffffu, sk, m);
        svq += __shfl_xor_sync(0xffffffffu, svq, m);
        svk += __shfl_xor_sync(0xffffffffu, svk, m);
    }
    float nq0 = sqrtf(fmaxf(sq, 1e-7f));
    float scq = fminf(3.0f / nq0, 1.0f);
    float nq  = sqrtf(fmaxf(sq * scq * scq, 1e-14f));
    float cq  = coshf(nq), fq = sinhf(nq) / nq * scq;

    float nk0 = sqrtf(fmaxf(sk, 1e-7f));
    float sck = fminf(3.0f / nk0, 1.0f);
    float nk  = sqrtf(fmaxf(sk * sck * sck, 1e-14f));
    float ck  = coshf(nk), fk = sinhf(nk) / nk * sck;

    int bh = b * CH + h;
    size_t base = ((size_t)bh * CN + n) * 128;
    const float R2 = 1.4142135623730951f;
    float fqi = fq * itc;
    sp2(g_Qs[0], g_Qs[1], base + lane * 2,      q.x * fqi, q.y * fqi);
    sp2(g_Qs[0], g_Qs[1], base + 64 + lane * 2, vq.x * R2, vq.y * R2);
    sp2(g_Ks[0], g_Ks[1], base + lane * 2,      k.x * fk,  k.y * fk);
    sp2(g_Ks[0], g_Ks[1], base + 64 + lane * 2, vk.x * R2, vk.y * R2);
    if (lane == 0) {
        int gi = bh * CN + n;
        g_su[gi]  = -cq * itc;
        g_swv[gi] = ck;
        g_cbv[gi] = itc - svk;
        g_rbv[gi] = -svq;
    }
}

// ---------------- MMA score: S = Q~K~^T + rank1 + biases + topo; row max ----------------
__global__ __launch_bounds__(256) void mma_score(const float* __restrict__ gam, float* __restrict__ S) {
    extern __shared__ char smem[];
    uint32_t sb = smem_u32(smem);
    int t = threadIdx.x, lane = t & 31, w = t >> 5;
    int m_warp = (w & 1) * 64, n_warp = (w >> 1) * 32;
    int bh = blockIdx.z, m0 = blockIdx.y * 128, n0 = blockIdx.x * 128;
    size_t qr0 = (size_t)bh * CN + m0, kr0 = (size_t)bh * CN + n0;

    float acc[4][4][4];
#pragma unroll
    for (int a = 0; a < 4; a++)
#pragma unroll
        for (int b = 0; b < 4; b++)
#pragma unroll
            for (int c = 0; c < 4; c++) acc[a][b][c] = 0.0f;

    for (int ch = 0; ch < 2; ch++) {
        int k0 = ch * 64;
        __syncthreads();
        load_plane(g_Qs[0], qr0, 128, k0, smem + 0 * PLANE);
        load_plane(g_Qs[1], qr0, 128, k0, smem + 1 * PLANE);
        load_plane(g_Ks[0], kr0, 128, k0, smem + 2 * PLANE);
        load_plane(g_Ks[1], kr0, 128, k0, smem + 3 * PLANE);
        __syncthreads();
        mma_chunk(acc, sb + 0 * PLANE, sb + 2 * PLANE, m_warp, n_warp, lane);
        mma_chunk(acc, sb + 0 * PLANE, sb + 3 * PLANE, m_warp, n_warp, lane);
        mma_chunk(acc, sb + 1 * PLANE, sb + 2 * PLANE, m_warp, n_warp, lane);
    }

    int h = bh & 7;
    float g0 = gam[h * 3 + 0], g1 = gam[h * 3 + 1], g2 = gam[h * 3 + 2];
    bool use23 = (g1 != 0.0f) || (g2 != 0.0f);
    int wordIdx = (n0 + n_warp) >> 5;

    // per-column terms for this thread's 8 columns
    float cw[4][2], sw[4][2];
#pragma unroll
    for (int ni = 0; ni < 4; ni++) {
        int gcol = bh * CN + n0 + n_warp + ni * 8 + (lane & 3) * 2;
        cw[ni][0] = g_cbv[gcol];     cw[ni][1] = g_cbv[gcol + 1];
        sw[ni][0] = g_swv[gcol];     sw[ni][1] = g_swv[gcol + 1];
    }

#pragma unroll
    for (int mi = 0; mi < 4; mi++) {
#pragma unroll
        for (int r2 = 0; r2 < 2; r2++) {
            int i = m0 + m_warp + mi * 16 + (lane >> 2) + r2 * 8;
            size_t gr = (size_t)bh * CN + i;
            float uu = g_su[gr], rb = g_rbv[gr];
            unsigned w1 = g_m1[i * 32 + wordIdx], w2 = 0, w3 = 0;
            if (use23) { w2 = g_m2[i * 32 + wordIdx]; w3 = g_m3[i * 32 + wordIdx]; }
            float rmax = -3.4e38f;
            float* Srow = S + gr * (size_t)CN + n0 + n_warp;
#pragma unroll
            for (int ni = 0; ni < 4; ni++) {
                int off = ni * 8 + (lane & 3) * 2;
                float2 o;
#pragma unroll
                for (int c = 0; c < 2; c++) {
                    int sh = off + c;
                    float s = acc[mi][ni][r2 * 2 + c] + uu * sw[ni][c] + cw[ni][c] + rb;
                    s += ((w1 >> sh) & 1) ? g0 : 0.0f;
                    if (use23) {
                        s += ((w2 >> sh) & 1) ? g1 : 0.0f;
                        s += ((w3 >> sh) & 1) ? g2 : 0.0f;
                    }
                    rmax = fmaxf(rmax, s);
                    (c == 0 ? o.x : o.y) = s;
                }
                *(float2*)(Srow + off) = o;
            }
            rmax = fmaxf(rmax, __shfl_xor_sync(0xffffffffu, rmax, 1));
            rmax = fmaxf(rmax, __shfl_xor_sync(0xffffffffu, rmax, 2));
            if ((lane & 3) == 0) atomicMax(&g_rowM[gr], fenc(rmax));
        }
    }
}

// ---------------- row sums of exp(S - M) ----------------
__global__ void k_rowsum(const float* __restrict__ S) {
    int row = blockIdx.x * 8 + (threadIdx.x >> 5);
    int lane = threadIdx.x & 31;
    float M = fdec(g_rowM[row]);
    const float* Sr = S + (size_t)row * CN;
    float sum = 0.0f;
#pragma unroll
    for (int w = 0; w < 8; w++) {
        float4 v = *(const float4*)(Sr + (w * 32 + lane) * 4);
        sum += __expf(v.x - M) + __expf(v.y - M) + __expf(v.z - M) + __expf(v.w - M);
    }
#pragma unroll
    for (int m = 16; m; m >>= 1) sum += __shfl_xor_sync(0xffffffffu, sum, m);
    if (lane == 0) g_rowZ[row] = sum;
}

// ---------------- normalize attn (write) + z = P @ v_s ----------------
__global__ __launch_bounds__(256) void k_zattn(float* __restrict__ S, float* __restrict__ z) {
    __shared__ float Vs[32 * 64];
    __shared__ float Ps[128 * 33];
    __shared__ float sM[128];
    __shared__ float sR[128];
    int t = threadIdx.x;
    int bh = blockIdx.y; int b = bh >> 3, h = bh & 7;
    int i0 = blockIdx.x * 128;
    if (t < 128) {
        int r = bh * CN + i0 + t;
        sM[t] = fdec(g_rowM[r]);
        sR[t] = 1.0f / g_rowZ[r];
    }
    int tx = t & 15, ty = t >> 4;
    ull acc[8][2];
#pragma unroll
    for (int i = 0; i < 8; i++) { acc[i][0] = 0ULL; acc[i][1] = 0ULL; }
    float* Sbase = S + ((size_t)bh * CN + i0) * CN;

    for (int k0 = 0; k0 < CN; k0 += 32) {
        __syncthreads();
        {
            int kk = t >> 3, fg = t & 7;
            const float* vr = g_x + (size_t)(b * CN + k0 + kk) * 1536 + 1024 + h * 64;
            *(float4*)(Vs + kk * 64 + fg * 4)      = *(const float4*)(vr + fg * 4);
            *(float4*)(Vs + kk * 64 + 32 + fg * 4) = *(const float4*)(vr + 32 + fg * 4);
        }
        {
            int r = t >> 1;
            float M = sM[r], ri = sR[r];
            float* Srow = Sbase + (size_t)r * CN + k0 + (t & 1) * 16;
            float* Prow = Ps + r * 33 + (t & 1) * 16;
#pragma unroll
            for (int w2 = 0; w2 < 4; w2++) {
                float4 v = *(float4*)(Srow + w2 * 4);
                v.x = __expf(v.x - M) * ri; v.y = __expf(v.y - M) * ri;
                v.z = __expf(v.z - M) * ri; v.w = __expf(v.w - M) * ri;
                *(float4*)(Srow + w2 * 4) = v;
                Prow[w2 * 4 + 0] = v.x; Prow[w2 * 4 + 1] = v.y;
                Prow[w2 * 4 + 2] = v.z; Prow[w2 * 4 + 3] = v.w;
            }
        }
        __syncthreads();
#pragma unroll 4
        for (int k = 0; k < 32; k++) {
            F4U vv; vv.f = *(const float4*)(Vs + k * 64 + tx * 4);
#pragma unroll
            for (int i = 0; i < 8; i++) {
                float p = Ps[(ty * 8 + i) * 33 + k];
                ull pb = bcast2(p);
                fma2(acc[i][0], pb, vv.u[0]);
                fma2(acc[i][1], pb, vv.u[1]);
            }
        }
    }
#pragma unroll
    for (int i = 0; i < 8; i++) {
        int n = i0 + ty * 8 + i;
        float2 a = unpk(acc[i][0]), c2 = unpk(acc[i][1]);
        float4 o = make_float4(a.x, a.y, c2.x, c2.y);
        *(float4*)(z + (size_t)(b * CN + n) * CD + h * 64 + tx * 4) = o;
    }
}

// ---------------- launch ----------------
extern "C" void kernel_launch(void* const* d_in, const int* in_sizes, int n_in,
                              void* d_out, int out_size) {
    const float* x_tan     = (const float*)d_in[0];
    const float* v_tan     = (const float*)d_in[1];
    const float* topo_bias = (const float*)d_in[2];
    const float* qkv_w     = (const float*)d_in[3];
    const float* qkv_b     = (const float*)d_in[4];
    const float* tau       = (const float*)d_in[5];
    const float* gam       = (const float*)d_in[6];
    float* z    = (float*)d_out;
    float* attn = z + (size_t)CB * CN * CD;

    cudaFuncSetAttribute(mma_qkv,   cudaFuncAttributeMaxDynamicSharedMemorySize, SMEM_BYTES);
    cudaFuncSetAttribute(mma_score, cudaFuncAttributeMaxDynamicSharedMemorySize, SMEM_BYTES);

    k_init<<<128, 256>>>();
    k_split<<<2048, 256>>>(x_tan, 0, CB * CN * 512 / 4);
    k_split<<<2048, 256>>>(v_tan, 1, CB * CN * 512 / 4);
    k_split<<<768, 256>>>(qkv_w, 2, 1536 * 512 / 4);
    mma_qkv<<<dim3(12, 32), 256, SMEM_BYTES>>>(qkv_b, 0, 1536);
    mma_qkv<<<dim3(8, 32), 256, SMEM_BYTES>>>(qkv_b, 1, 1024);
    k_bits1<<<128, 256>>>(topo_bias);
    k_bits2<<<128, 256>>>();
    k_bits3<<<128, 256>>>();
    k_augment<<<4096, 256>>>(tau);
    mma_score<<<dim3(8, 8, 32), 256, SMEM_BYTES>>>(gam, attn);
    k_rowsum<<<4096, 256>>>(attn);
    k_zattn<<<dim3(8, 32), 256>>>(attn, z);
}